// round 3
// baseline (speedup 1.0000x reference)
#include <cuda_runtime.h>

// out[i,j,:] = (i==j) ? 0 : A[min(i,j)] + B[max(i,j)] + b
// where A = x @ W[:, :256].T, B = x @ W[:, 256:].T
//
// Fused single-wave kernel: 528 blocks (one per upper-triangular 16x16 tile),
// all co-resident (occupancy 4/SM enforced). Blocks 0..127 additionally
// compute one 32x64 GEMM tile of C[512,512] = x @ Wt + 0.5*b first and
// signal per-16-row-group ready flags; every block then spin-waits for its
// two row groups and performs the broadcast-add expansion.

__device__ float g_C[512 * 512];   // 1 MB scratch (fits L2)
__device__ int   g_flag[32];       // per-16-row-group arrival count (target 8)
__device__ int   g_done;           // for self-reset at end of each launch

__global__ __launch_bounds__(256, 4)
void fused_kernel(const float* __restrict__ x,
                  const float* __restrict__ W,
                  const float* __restrict__ bias,
                  float4* __restrict__ out) {
    __shared__ float4 sAs[16][64];  // expand: A rows for i-tile (16 KB)
    __shared__ float4 sBs[16][64];  // expand: B rows for j-tile (16 KB)

    const int tid = threadIdx.x;
    const int bid = blockIdx.x;

    // ---------------- Phase 1: GEMM (blocks 0..127) ----------------
    if (bid < 128) {
        // overlay gemm staging inside sAs (needs 6 KB of its 16 KB)
        float* sA = (float*)sAs;            // [16][32]
        float* sB = ((float*)sAs) + 16 * 32; // [16][64]

        const int bx = bid & 7;             // N tile (64 wide)
        const int by = bid >> 3;            // M tile (32 tall), 0..15
        const int tx = tid & 15;            // n group (4 cols)
        const int ty = tid >> 4;            // m group (2 rows)

        const int lrow = tid >> 2;          // A: 0..31 (tid<128), B: 0..63
        const int lkq  = tid & 3;

        const int o = bx * 64 + lrow;
        const long wbase = (o < 256) ? (long)o * 512 : (long)(o - 256) * 512 + 256;
        const long xbase = (long)(by * 32 + lrow) * 256;  // valid for tid<128

        float acc[2][4];
#pragma unroll
        for (int m = 0; m < 2; m++)
#pragma unroll
            for (int n = 0; n < 4; n++) acc[m][n] = 0.0f;

        for (int k0 = 0; k0 < 256; k0 += 16) {
            float4 va = make_float4(0.f, 0.f, 0.f, 0.f);
            if (tid < 128) va = *(const float4*)&x[xbase + k0 + lkq * 4];
            float4 vb = *(const float4*)&W[wbase + k0 + lkq * 4];
            __syncthreads();
            if (tid < 128) {
                sA[(lkq * 4 + 0) * 32 + lrow] = va.x;
                sA[(lkq * 4 + 1) * 32 + lrow] = va.y;
                sA[(lkq * 4 + 2) * 32 + lrow] = va.z;
                sA[(lkq * 4 + 3) * 32 + lrow] = va.w;
            }
            sB[(lkq * 4 + 0) * 64 + lrow] = vb.x;
            sB[(lkq * 4 + 1) * 64 + lrow] = vb.y;
            sB[(lkq * 4 + 2) * 64 + lrow] = vb.z;
            sB[(lkq * 4 + 3) * 64 + lrow] = vb.w;
            __syncthreads();

#pragma unroll
            for (int kk = 0; kk < 16; kk++) {
                float2 a2 = *(const float2*)&sA[kk * 32 + ty * 2];
                float4 b4 = *(const float4*)&sB[kk * 64 + tx * 4];
                float am[2] = {a2.x, a2.y};
                float bn[4] = {b4.x, b4.y, b4.z, b4.w};
#pragma unroll
                for (int m = 0; m < 2; m++)
#pragma unroll
                    for (int n = 0; n < 4; n++)
                        acc[m][n] = fmaf(am[m], bn[n], acc[m][n]);
            }
        }

        float bb[4];
#pragma unroll
        for (int n = 0; n < 4; n++)
            bb[n] = 0.5f * bias[(bx * 64 + tx * 4 + n) & 255];

#pragma unroll
        for (int m = 0; m < 2; m++) {
            int row = by * 32 + ty * 2 + m;
            float4 v = make_float4(acc[m][0] + bb[0], acc[m][1] + bb[1],
                                   acc[m][2] + bb[2], acc[m][3] + bb[3]);
            *(float4*)&g_C[(long)row * 512 + bx * 64 + tx * 4] = v;
        }

        __threadfence();            // publish this block's C slice (per-thread)
        __syncthreads();
        if (tid == 0) {
            atomicAdd(&g_flag[2 * by], 1);
            atomicAdd(&g_flag[2 * by + 1], 1);
        }
    }

    // ---------------- Phase 2: expansion (all 528 blocks) ----------------
    // decode linear block id -> (ti, tj), ti <= tj
    int rem = bid;
    int ti = 0;
#pragma unroll 1
    while (rem >= 32 - ti) { rem -= 32 - ti; ti++; }
    const int tj = ti + rem;

    if (tid == 0) {
        while (__ldcg((const int*)&g_flag[ti]) < 8) __nanosleep(64);
        while (__ldcg((const int*)&g_flag[tj]) < 8) __nanosleep(64);
        __threadfence();            // order the flag read before C reads
    }
    __syncthreads();                // also retires the gemm shared overlay

    const float4* C4 = (const float4*)g_C;  // row = 128 float4 (A: 0..63, B: 64..127)
#pragma unroll
    for (int idx = tid; idx < 16 * 64; idx += 256) {
        int r = idx >> 6, c = idx & 63;
        sAs[r][c] = __ldcg(&C4[(long)(ti * 16 + r) * 128 + c]);
        sBs[r][c] = __ldcg(&C4[(long)(tj * 16 + r) * 128 + 64 + c]);
    }
    __syncthreads();

    const int o4 = tid & 63;       // which float4 of the 256-float feature row
    const int g  = tid >> 6;       // 0..3

    if (ti == tj) {
#pragma unroll 4
        for (int p = g; p < 256; p += 4) {
            int ii = p >> 4, jj = p & 15;
            int i = ti * 16 + ii, j = tj * 16 + jj;
            float4 v;
            if (ii == jj) {
                v = make_float4(0.f, 0.f, 0.f, 0.f);
            } else {
                int lo = min(ii, jj), hi = max(ii, jj);
                float4 a = sAs[lo][o4];
                float4 b = sBs[hi][o4];
                v = make_float4(a.x + b.x, a.y + b.y, a.z + b.z, a.w + b.w);
            }
            __stcs(&out[((long)i * 512 + j) * 64 + o4], v);
        }
    } else {
#pragma unroll 4
        for (int p = g; p < 256; p += 4) {
            int ii = p >> 4, jj = p & 15;
            int i = ti * 16 + ii, j = tj * 16 + jj;
            float4 a = sAs[ii][o4];
            float4 b = sBs[jj][o4];
            float4 v = make_float4(a.x + b.x, a.y + b.y, a.z + b.z, a.w + b.w);
            __stcs(&out[((long)i * 512 + j) * 64 + o4], v);
            __stcs(&out[((long)j * 512 + i) * 64 + o4], v);
        }
    }

    // ---------------- self-reset for next graph replay ----------------
    if (tid == 0) {
        int d = atomicAdd(&g_done, 1);
        if (d == 527) {             // last block: everyone has passed the waits
#pragma unroll
            for (int r = 0; r < 32; r++) g_flag[r] = 0;
            g_done = 0;
            __threadfence();
        }
    }
}

extern "C" void kernel_launch(void* const* d_in, const int* in_sizes, int n_in,
                              void* d_out, int out_size) {
    const float* x = (const float*)d_in[0];   // [512, 256]
    const float* W = (const float*)d_in[1];   // [256, 512]
    const float* b = (const float*)d_in[2];   // [256]

    fused_kernel<<<528, 256>>>(x, W, b, (float4*)d_out);
}

// round 4
// speedup vs baseline: 1.0875x; 1.0875x over previous
#include <cuda_runtime.h>

// out[i,j,:] = (i==j) ? 0 : A[min(i,j)] + B[max(i,j)] + b
// where A = x @ W[:, :256].T, B = x @ W[:, 256:].T
//
// Stage 1: C[512,512] = x[512,256] @ Wt[256,512] + 0.5*b
//          (Wt col o<256 -> W[o][k], o>=256 -> W[o-256][k+256])
//          256 blocks of 32x32 tiles, 64 threads, 4x4 microtile (2 B/FMA).
// Stage 2: broadcast-add expansion over 528 upper-triangular 16x16 tiles,
//          4 blocks/SM -> single wave.

__device__ float g_C[512 * 512];   // 1 MB scratch (fits L2)

__global__ __launch_bounds__(64, 8)
void gemm_kernel(const float* __restrict__ x,
                 const float* __restrict__ W,
                 const float* __restrict__ bias) {
    __shared__ float sA[8][32];    // [k][m]
    __shared__ float sB[8][32];    // [k][o]

    const int tid = threadIdx.x;   // 0..63
    const int tx = tid & 7;        // n group (4 cols)
    const int ty = tid >> 3;       // m group (4 rows)
    const int bx = blockIdx.x;     // N tile (32 wide), 0..15
    const int by = blockIdx.y;     // M tile (32 tall), 0..15

    // loaders: thread -> (row r = tid>>1, half h = tid&1), one float4 each from x and W
    const int lr = tid >> 1;       // 0..31
    const int lh = tid & 1;        // which float4 of the 8-wide k chunk

    const int o = bx * 32 + lr;
    const long wbase = (o < 256) ? (long)o * 512 : (long)(o - 256) * 512 + 256;
    const long xbase = (long)(by * 32 + lr) * 256;

    float acc[4][4];
#pragma unroll
    for (int m = 0; m < 4; m++)
#pragma unroll
        for (int n = 0; n < 4; n++) acc[m][n] = 0.0f;

    for (int k0 = 0; k0 < 256; k0 += 8) {
        float4 va = *(const float4*)&x[xbase + k0 + lh * 4];
        float4 vb = *(const float4*)&W[wbase + k0 + lh * 4];
        __syncthreads();           // protect previous iteration's reads
        sA[lh * 4 + 0][lr] = va.x;
        sA[lh * 4 + 1][lr] = va.y;
        sA[lh * 4 + 2][lr] = va.z;
        sA[lh * 4 + 3][lr] = va.w;
        sB[lh * 4 + 0][lr] = vb.x;
        sB[lh * 4 + 1][lr] = vb.y;
        sB[lh * 4 + 2][lr] = vb.z;
        sB[lh * 4 + 3][lr] = vb.w;
        __syncthreads();

#pragma unroll
        for (int kk = 0; kk < 8; kk++) {
            float4 a4 = *(const float4*)&sA[kk][ty * 4];
            float4 b4 = *(const float4*)&sB[kk][tx * 4];
            float am[4] = {a4.x, a4.y, a4.z, a4.w};
            float bn[4] = {b4.x, b4.y, b4.z, b4.w};
#pragma unroll
            for (int m = 0; m < 4; m++)
#pragma unroll
                for (int n = 0; n < 4; n++)
                    acc[m][n] = fmaf(am[m], bn[n], acc[m][n]);
        }
    }

    // epilogue: fold 0.5*b (full b re-assembles in the expansion sum)
    float bb[4];
#pragma unroll
    for (int n = 0; n < 4; n++)
        bb[n] = 0.5f * bias[(bx * 32 + tx * 4 + n) & 255];

#pragma unroll
    for (int m = 0; m < 4; m++) {
        int row = by * 32 + ty * 4 + m;
        float4 v = make_float4(acc[m][0] + bb[0], acc[m][1] + bb[1],
                               acc[m][2] + bb[2], acc[m][3] + bb[3]);
        *(float4*)&g_C[(long)row * 512 + bx * 32 + tx * 4] = v;
    }
}

// 528 blocks = exactly the upper-triangular 16x16 cell tiles (ti <= tj).
// 4 blocks/SM (regs capped at 64) -> all blocks in one wave.
__global__ __launch_bounds__(256, 4)
void expand_kernel(float4* __restrict__ out) {
    // decode linear block id -> (ti, tj), ti <= tj, row ti has (32 - ti) tiles
    int rem = blockIdx.x;
    int ti = 0;
#pragma unroll 1
    while (rem >= 32 - ti) { rem -= 32 - ti; ti++; }
    const int tj = ti + rem;

    __shared__ float4 sAs[16][64];  // A rows for i-tile   (16 KB)
    __shared__ float4 sBs[16][64];  // B rows for j-tile   (16 KB)

    const int tid = threadIdx.x;
    const float4* C4 = (const float4*)g_C;   // row = 128 float4 (A: 0..63, B: 64..127)

#pragma unroll
    for (int idx = tid; idx < 16 * 64; idx += 256) {
        int r = idx >> 6, c = idx & 63;
        sAs[r][c] = C4[(long)(ti * 16 + r) * 128 + c];
        sBs[r][c] = C4[(long)(tj * 16 + r) * 128 + 64 + c];
    }
    __syncthreads();

    const int o4 = tid & 63;       // which float4 of the 256-float feature row
    const int g  = tid >> 6;       // 0..3

    if (ti == tj) {
        // diagonal tile: each (ii,jj) pair writes exactly its own cell
#pragma unroll 2
        for (int p = g; p < 256; p += 4) {
            int ii = p >> 4, jj = p & 15;
            int i = ti * 16 + ii, j = tj * 16 + jj;
            float4 v;
            if (ii == jj) {
                v = make_float4(0.f, 0.f, 0.f, 0.f);
            } else {
                int lo = min(ii, jj), hi = max(ii, jj);
                float4 a = sAs[lo][o4];
                float4 b = sBs[hi][o4];
                v = make_float4(a.x + b.x, a.y + b.y, a.z + b.z, a.w + b.w);
            }
            __stcs(&out[((long)i * 512 + j) * 64 + o4], v);
        }
    } else {
        // strictly-upper tile: i < j always; write (i,j) and its mirror (j,i)
#pragma unroll 2
        for (int p = g; p < 256; p += 4) {
            int ii = p >> 4, jj = p & 15;
            int i = ti * 16 + ii, j = tj * 16 + jj;
            float4 a = sAs[ii][o4];
            float4 b = sBs[jj][o4];
            float4 v = make_float4(a.x + b.x, a.y + b.y, a.z + b.z, a.w + b.w);
            __stcs(&out[((long)i * 512 + j) * 64 + o4], v);
            __stcs(&out[((long)j * 512 + i) * 64 + o4], v);
        }
    }
}

extern "C" void kernel_launch(void* const* d_in, const int* in_sizes, int n_in,
                              void* d_out, int out_size) {
    const float* x = (const float*)d_in[0];   // [512, 256]
    const float* W = (const float*)d_in[1];   // [256, 512]
    const float* b = (const float*)d_in[2];   // [256]

    gemm_kernel<<<dim3(16, 16), 64>>>(x, W, b);
    expand_kernel<<<528, 256>>>((float4*)d_out);
}

// round 5
// speedup vs baseline: 1.3238x; 1.2173x over previous
#include <cuda_runtime.h>

// out[i,j,:] = (i==j) ? 0 : A[min(i,j)] + B[max(i,j)] + b
// where A = x @ W[:, :256].T, B = x @ W[:, 256:].T
//
// Stage 1 (split-K=2): g_C[kz][512,512] = x[:, kz*128:+128] @ Wt[kz half] + 0.25*b
//   128 blocks (8 bx x 8 by x 2 kz), 128 threads, 64x64 tile,
//   8x4 microtile with packed fma.rn.f32x2 (beats the FFMA rt_SMSP=2 issue cap),
//   double-buffered smem to hide LDG latency.
// Stage 2: broadcast-add expansion over 528 upper-triangular 16x16 tiles,
//   summing both C halves (exact R2 body otherwise).

__device__ float g_C[2][512 * 512];   // 2 MB scratch (fits L2)

__device__ __forceinline__ unsigned long long fma2(unsigned long long a,
                                                   unsigned long long b,
                                                   unsigned long long c) {
    unsigned long long d;
    asm("fma.rn.f32x2 %0, %1, %2, %3;" : "=l"(d) : "l"(a), "l"(b), "l"(c));
    return d;
}
__device__ __forceinline__ unsigned long long packf2(float v) {
    unsigned long long r;
    asm("mov.b64 %0, {%1, %1};" : "=l"(r) : "f"(v));
    return r;
}
__device__ __forceinline__ void unpackf2(unsigned long long v, float& lo, float& hi) {
    asm("mov.b64 {%0, %1}, %2;" : "=f"(lo), "=f"(hi) : "l"(v));
}

__global__ __launch_bounds__(128, 2)
void gemm_kernel(const float* __restrict__ x,
                 const float* __restrict__ W,
                 const float* __restrict__ bias) {
    __shared__ float sA[2][8][64];   // [buf][k][m]
    __shared__ float sB[2][8][64];   // [buf][k][o]

    const int tid = threadIdx.x;     // 0..127
    const int tx = tid & 15;         // n group (4 cols): n0 = tx*4
    const int ty = tid >> 4;         // m group (8 rows): m0 = ty*8
    const int bx = blockIdx.x;       // N tile (64 wide), 0..7
    const int by = blockIdx.y;       // M tile (64 tall), 0..7
    const int kz = blockIdx.z;       // K half, 0..1

    const int lr = tid >> 1;         // 0..63 (row within tile)
    const int lh = tid & 1;          // which float4 of the 8-wide k chunk

    const int o = bx * 64 + lr;
    const long wrow = (o < 256) ? (long)o * 512 : (long)(o - 256) * 512 + 256;
    const long xrow = (long)(by * 64 + lr) * 256;
    const int kbase = kz * 128;

    unsigned long long acc[4][4];    // [m-pair][n], each packs rows (2mp, 2mp+1)
#pragma unroll
    for (int m = 0; m < 4; m++)
#pragma unroll
        for (int n = 0; n < 4; n++) acc[m][n] = 0ull;

    // prologue: load chunk 0 into buffer 0
    float4 va = *(const float4*)&x[xrow + kbase + lh * 4];
    float4 vb = *(const float4*)&W[wrow + kbase + lh * 4];
#pragma unroll
    {
        sA[0][lh * 4 + 0][lr] = va.x;
        sA[0][lh * 4 + 1][lr] = va.y;
        sA[0][lh * 4 + 2][lr] = va.z;
        sA[0][lh * 4 + 3][lr] = va.w;
        sB[0][lh * 4 + 0][lr] = vb.x;
        sB[0][lh * 4 + 1][lr] = vb.y;
        sB[0][lh * 4 + 2][lr] = vb.z;
        sB[0][lh * 4 + 3][lr] = vb.w;
    }
    __syncthreads();

#pragma unroll 1
    for (int c = 0; c < 16; c++) {
        const int cur = c & 1;
        // prefetch next chunk into registers (overlaps with compute below)
        if (c < 15) {
            int k0 = kbase + (c + 1) * 8;
            va = *(const float4*)&x[xrow + k0 + lh * 4];
            vb = *(const float4*)&W[wrow + k0 + lh * 4];
        }

#pragma unroll
        for (int kk = 0; kk < 8; kk++) {
            const ulonglong2* pa = (const ulonglong2*)&sA[cur][kk][ty * 8];
            ulonglong2 q0 = pa[0];            // rows m0..m0+3 (2 packed pairs)
            ulonglong2 q1 = pa[1];            // rows m0+4..m0+7
            float4 b4 = *(const float4*)&sB[cur][kk][tx * 4];
            unsigned long long bb[4] = {packf2(b4.x), packf2(b4.y),
                                        packf2(b4.z), packf2(b4.w)};
#pragma unroll
            for (int n = 0; n < 4; n++) {
                acc[0][n] = fma2(q0.x, bb[n], acc[0][n]);
                acc[1][n] = fma2(q0.y, bb[n], acc[1][n]);
                acc[2][n] = fma2(q1.x, bb[n], acc[2][n]);
                acc[3][n] = fma2(q1.y, bb[n], acc[3][n]);
            }
        }

        if (c < 15) {
            const int nxt = cur ^ 1;
            __syncthreads();   // retire readers of buffer nxt (chunk c-1)
            sA[nxt][lh * 4 + 0][lr] = va.x;
            sA[nxt][lh * 4 + 1][lr] = va.y;
            sA[nxt][lh * 4 + 2][lr] = va.z;
            sA[nxt][lh * 4 + 3][lr] = va.w;
            sB[nxt][lh * 4 + 0][lr] = vb.x;
            sB[nxt][lh * 4 + 1][lr] = vb.y;
            sB[nxt][lh * 4 + 2][lr] = vb.z;
            sB[nxt][lh * 4 + 3][lr] = vb.w;
            __syncthreads();   // publish chunk c+1
        }
    }

    // epilogue: fold 0.25*b per split (4 contributions re-assemble full b)
    float bb4[4];
#pragma unroll
    for (int n = 0; n < 4; n++)
        bb4[n] = 0.25f * bias[(bx * 64 + tx * 4 + n) & 255];

    float* Cdst = g_C[kz];
#pragma unroll
    for (int mp = 0; mp < 4; mp++) {
        float lo[4], hi[4];
#pragma unroll
        for (int n = 0; n < 4; n++) unpackf2(acc[mp][n], lo[n], hi[n]);
        int row0 = by * 64 + ty * 8 + mp * 2;
        float4 v0 = make_float4(lo[0] + bb4[0], lo[1] + bb4[1],
                                lo[2] + bb4[2], lo[3] + bb4[3]);
        float4 v1 = make_float4(hi[0] + bb4[0], hi[1] + bb4[1],
                                hi[2] + bb4[2], hi[3] + bb4[3]);
        *(float4*)&Cdst[(long)row0 * 512 + bx * 64 + tx * 4] = v0;
        *(float4*)&Cdst[(long)(row0 + 1) * 512 + bx * 64 + tx * 4] = v1;
    }
}

// 528 blocks = exactly the upper-triangular 16x16 cell tiles (ti <= tj).
__global__ __launch_bounds__(256, 1)
void expand_kernel(float4* __restrict__ out) {
    // decode linear block id -> (ti, tj), ti <= tj, row ti has (32 - ti) tiles
    int rem = blockIdx.x;
    int ti = 0;
#pragma unroll 1
    while (rem >= 32 - ti) { rem -= 32 - ti; ti++; }
    const int tj = ti + rem;

    __shared__ float4 sAs[16][64];  // A rows for i-tile   (16 KB)
    __shared__ float4 sBs[16][64];  // B rows for j-tile   (16 KB)

    const int tid = threadIdx.x;
    const float4* C0 = (const float4*)g_C[0];   // row = 128 float4 (A: 0..63, B: 64..127)
    const float4* C1 = (const float4*)g_C[1];

#pragma unroll
    for (int idx = tid; idx < 16 * 64; idx += 256) {
        int r = idx >> 6, c = idx & 63;
        float4 a0 = C0[(long)(ti * 16 + r) * 128 + c];
        float4 a1 = C1[(long)(ti * 16 + r) * 128 + c];
        float4 b0 = C0[(long)(tj * 16 + r) * 128 + 64 + c];
        float4 b1 = C1[(long)(tj * 16 + r) * 128 + 64 + c];
        sAs[r][c] = make_float4(a0.x + a1.x, a0.y + a1.y, a0.z + a1.z, a0.w + a1.w);
        sBs[r][c] = make_float4(b0.x + b1.x, b0.y + b1.y, b0.z + b1.z, b0.w + b1.w);
    }
    __syncthreads();

    const int o4 = tid & 63;       // which float4 of the 256-float feature row
    const int g  = tid >> 6;       // 0..3

    if (ti == tj) {
        // diagonal tile: each (ii,jj) pair writes exactly its own cell
#pragma unroll 4
        for (int p = g; p < 256; p += 4) {
            int ii = p >> 4, jj = p & 15;
            int i = ti * 16 + ii, j = tj * 16 + jj;
            float4 v;
            if (ii == jj) {
                v = make_float4(0.f, 0.f, 0.f, 0.f);
            } else {
                int lo = min(ii, jj), hi = max(ii, jj);
                float4 a = sAs[lo][o4];
                float4 b = sBs[hi][o4];
                v = make_float4(a.x + b.x, a.y + b.y, a.z + b.z, a.w + b.w);
            }
            __stcs(&out[((long)i * 512 + j) * 64 + o4], v);
        }
    } else {
        // strictly-upper tile: i < j always; write (i,j) and its mirror (j,i)
#pragma unroll 4
        for (int p = g; p < 256; p += 4) {
            int ii = p >> 4, jj = p & 15;
            int i = ti * 16 + ii, j = tj * 16 + jj;
            float4 a = sAs[ii][o4];
            float4 b = sBs[jj][o4];
            float4 v = make_float4(a.x + b.x, a.y + b.y, a.z + b.z, a.w + b.w);
            __stcs(&out[((long)i * 512 + j) * 64 + o4], v);
            __stcs(&out[((long)j * 512 + i) * 64 + o4], v);
        }
    }
}

extern "C" void kernel_launch(void* const* d_in, const int* in_sizes, int n_in,
                              void* d_out, int out_size) {
    const float* x = (const float*)d_in[0];   // [512, 256]
    const float* W = (const float*)d_in[1];   // [256, 512]
    const float* b = (const float*)d_in[2];   // [256]

    gemm_kernel<<<dim3(8, 8, 2), 128>>>(x, W, b);
    expand_kernel<<<528, 256>>>((float4*)d_out);
}